// round 5
// baseline (speedup 1.0000x reference)
#include <cuda_runtime.h>
#include <cstdint>
#include <cstddef>

#define T_SEQ 384
#define PRE_W 2048
#define ROWS_TOT 768

__device__ float g_pre0[ROWS_TOT * PRE_W];
__device__ float g_pre1[ROWS_TOT * PRE_W];
__device__ float g_x1  [ROWS_TOT * 512];
__device__ float g_lout[ROWS_TOT * 512];
__device__ float g_h1  [ROWS_TOT * 1024];
__device__ float g_h2  [ROWS_TOT * 512];
__device__ float g_u   [ROWS_TOT * 1024];
__device__ float g_W3s [1024 * 512];
__device__ float g_b1s [2048];

__device__ __forceinline__ float fsig(float x)  { return __fdividef(1.0f, 1.0f + __expf(-x)); }
__device__ __forceinline__ float ftanh_(float x){ return __fdividef(2.0f, 1.0f + __expf(-2.0f * x)) - 1.0f; }

// W3s[n][k] = W3[n][k] + W3[n][512+k]; b1s = bih1 + bhh1
__global__ void prep_kernel(const float* __restrict__ W3,
                            const float* __restrict__ bih1, const float* __restrict__ bhh1) {
    int idx = blockIdx.x * 256 + threadIdx.x;
    for (int i = idx; i < 1024 * 512; i += gridDim.x * 256) {
        int n = i >> 9, k = i & 511;
        g_W3s[i] = W3[n * 1024 + k] + W3[n * 1024 + 512 + k];
    }
    if (idx < 2048) g_b1s[idx] = bih1[idx] + bhh1[idx];
}

// pre0[row = seq*384+t][dir*1024 + gaterow] = v[t] . Wih0[dir][gaterow] + b
__global__ void pre0_kernel(const float* __restrict__ vr, const float* __restrict__ vl,
                            const float* __restrict__ Wih0,
                            const float* __restrict__ bih0, const float* __restrict__ bhh0) {
    __shared__ float vs[22];
    int row = blockIdx.x;
    int col = blockIdx.y * 128 + threadIdx.x;
    int seq = (row >= 384) ? 1 : 0;
    int t = row - seq * 384;
    const float* v = seq ? vl : vr;
    if (threadIdx.x < 22) vs[threadIdx.x] = v[t * 22 + threadIdx.x];
    __syncthreads();
    const float* w = Wih0 + (size_t)col * 22;
    float acc = bih0[col] + bhh0[col];
#pragma unroll
    for (int k = 0; k < 22; k++) acc += vs[k] * w[k];
    g_pre0[(size_t)row * PRE_W + col] = acc;
}

// 4 chains (seq,dir), one 8-CTA cluster per chain. rank owns h[32r..32r+32).
// thread: out = tid>>2 (gidx*32+e), seg = tid&3 (64-wide k segment), 64 weights in regs.
__global__ void __cluster_dims__(8, 1, 1) __launch_bounds__(512, 1)
lstm_kernel(const float* __restrict__ Whh, int layer) {
    __shared__ __align__(16) float hbuf[2][4 * 72];
    __shared__ float gates[128];

    const float* pre = layer ? g_pre1 : g_pre0;
    float* outp      = layer ? g_lout : g_x1;

    int tid = threadIdx.x;
    int rank = blockIdx.x & 7;
    int chain = blockIdx.x >> 3;
    int seq = chain >> 1, dir = chain & 1;
    int out = tid >> 2, seg = tid & 3;
    int gidx = out >> 5, e = out & 31;
    int row = gidx * 256 + rank * 32 + e;

    float w[64];
    {
        const float* wp = Whh + ((size_t)dir * 1024 + row) * 256 + seg * 64;
#pragma unroll
        for (int j = 0; j < 64; j += 4) {
            float4 t4 = *(const float4*)(wp + j);
            w[j] = t4.x; w[j+1] = t4.y; w[j+2] = t4.z; w[j+3] = t4.w;
        }
    }
    for (int i = tid; i < 4 * 72; i += 512) hbuf[0][i] = 0.0f;
    __syncthreads();

    float c = 0.0f;
    int p = 0;
    const float* preBase = pre + (size_t)(seq * T_SEQ) * PRE_W + dir * 1024 + row;
    float* outBase = outp + (size_t)(seq * T_SEQ) * 512 + dir * 256 + rank * 32;

    for (int t = 0; t < T_SEQ; t++) {
        int tt = dir ? (T_SEQ - 1 - t) : t;
        float pv = __ldg(preBase + (size_t)tt * PRE_W);

        const float4* hp = (const float4*)(&hbuf[p][seg * 72]);
        float a0 = 0.f, a1 = 0.f, a2 = 0.f, a3 = 0.f;
#pragma unroll
        for (int j = 0; j < 16; j++) {
            float4 hv = hp[j];
            a0 += w[4*j+0] * hv.x;
            a1 += w[4*j+1] * hv.y;
            a2 += w[4*j+2] * hv.z;
            a3 += w[4*j+3] * hv.w;
        }
        float acc = (a0 + a1) + (a2 + a3);
        acc += __shfl_xor_sync(0xffffffffu, acc, 1);
        acc += __shfl_xor_sync(0xffffffffu, acc, 2);
        float x = acc + pv;
        float av = (gidx == 2) ? ftanh_(x) : fsig(x);
        if (seg == 0) gates[out] = av;
        __syncthreads();

        if (tid < 32) {
            float gi = gates[tid], gf = gates[32 + tid], gg = gates[64 + tid], go = gates[96 + tid];
            c = gf * c + gi * gg;
            float hv = go * ftanh_(c);
            outBase[(size_t)tt * 512 + tid] = hv;
            int k = rank * 32 + tid;
            float* dst = &hbuf[p ^ 1][(k >> 6) * 72 + (k & 63)];
            uint32_t la = (uint32_t)__cvta_generic_to_shared(dst);
#pragma unroll
            for (int r = 0; r < 8; r++) {
                asm volatile(
                    "{\n\t.reg .b32 ra;\n\t"
                    "mapa.shared::cluster.u32 ra, %0, %1;\n\t"
                    "st.shared::cluster.f32 [ra], %2;\n\t}"
                    :: "r"(la), "r"(r), "f"(hv) : "memory");
            }
        }
        asm volatile("barrier.cluster.arrive.aligned;" ::: "memory");
        asm volatile("barrier.cluster.wait.aligned;"   ::: "memory");
        p ^= 1;
    }
}

// C[M,N] = epi(A[M,K] @ B[N,K]^T). MODE 0:+bias  1:relu(+bias)  2:0.5*acc + (row<384?bias:0)
template <int MODE>
__global__ void __launch_bounds__(256) gemm_kernel(
    const float* __restrict__ A, const float* __restrict__ B, const float* __restrict__ bias,
    float* __restrict__ C, int M, int N, int K) {
    __shared__ __align__(16) float As[16][68];
    __shared__ __align__(16) float Bs[16][68];
    int tid = threadIdx.x;
    int bm = blockIdx.y * 64, bn = blockIdx.x * 64;
    int tx = tid & 15, ty = tid >> 4;
    int lr = tid >> 2, lc = (tid & 3) * 4;

    const float* Ap = A + (size_t)(bm + lr) * K + lc;
    const float* Bp = B + (size_t)(bn + lr) * K + lc;
    float acc[4][4] = {};
    float4 ra = *(const float4*)Ap;
    float4 rb = *(const float4*)Bp;
    int nk = K >> 4;
    for (int kt = 0; kt < nk; kt++) {
        As[lc+0][lr] = ra.x; As[lc+1][lr] = ra.y; As[lc+2][lr] = ra.z; As[lc+3][lr] = ra.w;
        Bs[lc+0][lr] = rb.x; Bs[lc+1][lr] = rb.y; Bs[lc+2][lr] = rb.z; Bs[lc+3][lr] = rb.w;
        __syncthreads();
        if (kt + 1 < nk) {
            ra = *(const float4*)(Ap + (kt + 1) * 16);
            rb = *(const float4*)(Bp + (kt + 1) * 16);
        }
#pragma unroll
        for (int kk = 0; kk < 16; kk++) {
            float4 a4 = *(const float4*)&As[kk][ty * 4];
            float4 b4 = *(const float4*)&Bs[kk][tx * 4];
            acc[0][0] += a4.x*b4.x; acc[0][1] += a4.x*b4.y; acc[0][2] += a4.x*b4.z; acc[0][3] += a4.x*b4.w;
            acc[1][0] += a4.y*b4.x; acc[1][1] += a4.y*b4.y; acc[1][2] += a4.y*b4.z; acc[1][3] += a4.y*b4.w;
            acc[2][0] += a4.z*b4.x; acc[2][1] += a4.z*b4.y; acc[2][2] += a4.z*b4.z; acc[2][3] += a4.z*b4.w;
            acc[3][0] += a4.w*b4.x; acc[3][1] += a4.w*b4.y; acc[3][2] += a4.w*b4.z; acc[3][3] += a4.w*b4.w;
        }
        __syncthreads();
    }
    float bj0 = bias[bn + tx*4 + 0], bj1 = bias[bn + tx*4 + 1];
    float bj2 = bias[bn + tx*4 + 2], bj3 = bias[bn + tx*4 + 3];
#pragma unroll
    for (int i = 0; i < 4; i++) {
        int grow = bm + ty * 4 + i;
        float4 o;
        if (MODE == 0) {
            o.x = acc[i][0]+bj0; o.y = acc[i][1]+bj1; o.z = acc[i][2]+bj2; o.w = acc[i][3]+bj3;
        } else if (MODE == 1) {
            o.x = fmaxf(acc[i][0]+bj0, 0.f); o.y = fmaxf(acc[i][1]+bj1, 0.f);
            o.z = fmaxf(acc[i][2]+bj2, 0.f); o.w = fmaxf(acc[i][3]+bj3, 0.f);
        } else {
            float s = (grow < 384) ? 1.f : 0.f;
            o.x = 0.5f*acc[i][0] + s*bj0; o.y = 0.5f*acc[i][1] + s*bj1;
            o.z = 0.5f*acc[i][2] + s*bj2; o.w = 0.5f*acc[i][3] + s*bj3;
        }
        *(float4*)&C[(size_t)grow * N + bn + tx * 4] = o;
    }
}

// d(i,j) = sum_h relu(u[i,h]+u[384+j,h]) * (Wout[1,h]-Wout[0,h]) + db; out = {-l, d-l}, l=log(1+e^d)
__global__ void __launch_bounds__(256) pair_kernel(
    const float* __restrict__ Wout, const float* __restrict__ bout, float* __restrict__ outp) {
    __shared__ __align__(16) float urs[16][136];
    __shared__ __align__(16) float uls[16][136];
    __shared__ __align__(16) float dws[128];
    int tid = threadIdx.x;
    int bi = blockIdx.y * 16, bj = blockIdx.x * 16;
    int ti = tid >> 4, tj = tid & 15;
    int lr = tid >> 4, lc = (tid & 15) * 8;
    float d = bout[1] - bout[0];
    for (int hc = 0; hc < 1024; hc += 128) {
        __syncthreads();
        *(float4*)&urs[lr][lc]   = *(const float4*)&g_u[(size_t)(bi + lr) * 1024 + hc + lc];
        *(float4*)&urs[lr][lc+4] = *(const float4*)&g_u[(size_t)(bi + lr) * 1024 + hc + lc + 4];
        *(float4*)&uls[lr][lc]   = *(const float4*)&g_u[(size_t)(384 + bj + lr) * 1024 + hc + lc];
        *(float4*)&uls[lr][lc+4] = *(const float4*)&g_u[(size_t)(384 + bj + lr) * 1024 + hc + lc + 4];
        if (tid < 128) dws[tid] = Wout[1024 + hc + tid] - Wout[hc + tid];
        __syncthreads();
#pragma unroll 8
        for (int k = 0; k < 128; k += 4) {
            float4 a = *(const float4*)&urs[ti][k];
            float4 b = *(const float4*)&uls[tj][k];
            float4 w4 = *(const float4*)&dws[k];
            d += fmaxf(a.x + b.x, 0.f) * w4.x;
            d += fmaxf(a.y + b.y, 0.f) * w4.y;
            d += fmaxf(a.z + b.z, 0.f) * w4.z;
            d += fmaxf(a.w + b.w, 0.f) * w4.w;
        }
    }
    float m = fmaxf(d, 0.f);
    float l = m + __logf(__expf(0.f - m) + __expf(d - m));
    float2 o; o.x = -l; o.y = d - l;
    *(float2*)&outp[((size_t)(bi + ti) * 384 + (bj + tj)) * 2] = o;
}

extern "C" void kernel_launch(void* const* d_in, const int* in_sizes, int n_in,
                              void* d_out, int out_size) {
    const float* v_r  = (const float*)d_in[0];
    const float* v_l  = (const float*)d_in[1];
    const float* Wih0 = (const float*)d_in[2];
    const float* Whh0 = (const float*)d_in[3];
    const float* bih0 = (const float*)d_in[4];
    const float* bhh0 = (const float*)d_in[5];
    const float* Wih1 = (const float*)d_in[6];
    const float* Whh1 = (const float*)d_in[7];
    const float* bih1 = (const float*)d_in[8];
    const float* bhh1 = (const float*)d_in[9];
    const float* W1   = (const float*)d_in[10];
    const float* b1   = (const float*)d_in[11];
    const float* W2   = (const float*)d_in[12];
    const float* b2   = (const float*)d_in[13];
    const float* W3   = (const float*)d_in[14];
    const float* b3   = (const float*)d_in[15];
    const float* Wout = (const float*)d_in[16];
    const float* bout = (const float*)d_in[17];
    float* outp = (float*)d_out;

    void *p_x1, *p_lout, *p_h1, *p_h2, *p_u, *p_W3s, *p_b1s, *p_pre1;
    cudaGetSymbolAddress(&p_x1,   g_x1);
    cudaGetSymbolAddress(&p_lout, g_lout);
    cudaGetSymbolAddress(&p_h1,   g_h1);
    cudaGetSymbolAddress(&p_h2,   g_h2);
    cudaGetSymbolAddress(&p_u,    g_u);
    cudaGetSymbolAddress(&p_W3s,  g_W3s);
    cudaGetSymbolAddress(&p_b1s,  g_b1s);
    cudaGetSymbolAddress(&p_pre1, g_pre1);

    prep_kernel<<<148, 256>>>(W3, bih1, bhh1);
    pre0_kernel<<<dim3(ROWS_TOT, 16), 128>>>(v_r, v_l, Wih0, bih0, bhh0);
    lstm_kernel<<<32, 512>>>(Whh0, 0);
    // pre1 = x1 @ Wih1^T + b1s : M=768, N=2048, K=512
    gemm_kernel<0><<<dim3(32, 12), 256>>>((const float*)p_x1, Wih1, (const float*)p_b1s,
                                          (float*)p_pre1, 768, 2048, 512);
    lstm_kernel<<<32, 512>>>(Whh1, 1);
    // h1 = relu(lout @ W1^T + b1) : 768 x 1024, K=512
    gemm_kernel<1><<<dim3(16, 12), 256>>>((const float*)p_lout, W1, b1,
                                          (float*)p_h1, 768, 1024, 512);
    // h2 = relu(h1 @ W2^T + b2) : 768 x 512, K=1024
    gemm_kernel<1><<<dim3(8, 12), 256>>>((const float*)p_h1, W2, b2,
                                         (float*)p_h2, 768, 512, 1024);
    // u = 0.5*(h2 @ W3s^T) (+ b3 for rows<384) : 768 x 1024, K=512
    gemm_kernel<2><<<dim3(16, 12), 256>>>((const float*)p_h2, (const float*)p_W3s, b3,
                                          (float*)p_u, 768, 1024, 512);
    pair_kernel<<<dim3(24, 24), 256>>>(Wout, bout, outp);
}